// round 3
// baseline (speedup 1.0000x reference)
#include <cuda_runtime.h>
#include <math.h>

#define NLAYER 5
#define HID    128
#define BAT    32
#define TIN    512
#define TTOT   514     // 512 given + 2 autoregressive continuation steps
#define NB0    16      // blocks for layer 0
#define NBL    32      // blocks for layers 1..4
#define HEAD_BID 144
#define GRID_N 145
#define NTHR   256

// persistent device state (allocation-free scratch)
__device__ float g_h[NLAYER][TTOT][HID][BAT];   // hidden states, [k][b]
__device__ float g_xpred[2][BAT];               // predicted inputs for t=512,513
__device__ int   g_hflag[NLAYER][TTOT];         // completion counters
__device__ int   g_xflag[2];

__global__ void zero_flags_kernel() {
    int i = blockIdx.x * blockDim.x + threadIdx.x;
    if (i < NLAYER * TTOT) ((int*)g_hflag)[i] = 0;
    if (i < 2) g_xflag[i] = 0;
}

__device__ __forceinline__ float2 ffma2(float w, float2 h, float2 acc) {
    union { float2 f; unsigned long long u; } A, B, C, D;
    A.f = make_float2(w, w); B.f = h; C.f = acc;
    asm("fma.rn.f32x2 %0, %1, %2, %3;" : "=l"(D.u) : "l"(A.u), "l"(B.u), "l"(C.u));
    return D.f;
}

__device__ __forceinline__ void waitflag(volatile int* p, int tgt) {
    while (*p < tgt) __nanosleep(64);
}

__device__ __forceinline__ float sigm(float v) { return 1.0f / (1.0f + expf(-v)); }

__global__ void __launch_bounds__(NTHR, 1) lstm_main(
    const float* __restrict__ x,    const float* __restrict__ Wih0,
    const float* __restrict__ Wihr, const float* __restrict__ Whh,
    const float* __restrict__ bih,  const float* __restrict__ bhh,
    const float* __restrict__ W1,   const float* __restrict__ b1,
    const float* __restrict__ W2,   const float* __restrict__ b2,
    float* __restrict__ out)
{
    __shared__ float  sW[4224];   // weight slice (LSTM) / zsm (head, 32x129)
    __shared__ float  sH[4224];   // h staging (LSTM)    / z2sm (head, 32x129)
    __shared__ float  sB[32];     // combined biases
    __shared__ float  sWx[32];    // layer0 input weights
    __shared__ float2 sG[512];    // gate exchange

    const int tid = threadIdx.x;
    const int bid = blockIdx.x;

    // ================= HEAD BLOCK =================
    if (bid == HEAD_BID) {
        float* zsm  = sW;
        float* z2sm = sH;
        for (int m = 0; m < 3; m++) {
            int t = 511 + m;
            if (tid == 0) waitflag(&g_hflag[4][t], NBL);
            __syncthreads();
            // z = relu(h4[t]), transpose [k][b] -> zsm[b][k] (pad 129)
            for (int i = tid; i < HID * BAT; i += NTHR) {
                int k = i >> 5, b = i & 31;
                zsm[b * 129 + k] = fmaxf(g_h[4][t][k][b], 0.0f);
            }
            __syncthreads();
            // z2 = relu(z @ W1 + b1): thread (jgroup, b)
            {
                int jg = tid >> 5, b = tid & 31;
                float acc[16];
                #pragma unroll
                for (int jj = 0; jj < 16; jj++) acc[jj] = b1[jg * 16 + jj];
                for (int k = 0; k < HID; k++) {
                    float zv = zsm[b * 129 + k];
                    const float4* wr = (const float4*)(W1 + k * HID + jg * 16);
                    #pragma unroll
                    for (int q = 0; q < 4; q++) {
                        float4 w = wr[q];
                        acc[q*4+0] += w.x * zv; acc[q*4+1] += w.y * zv;
                        acc[q*4+2] += w.z * zv; acc[q*4+3] += w.w * zv;
                    }
                }
                #pragma unroll
                for (int jj = 0; jj < 16; jj++)
                    z2sm[b * 129 + jg * 16 + jj] = fmaxf(acc[jj], 0.0f);
            }
            __syncthreads();
            // out = z2 @ W2 + b2
            for (int cc = tid; cc < BAT * 16; cc += NTHR) {
                int ob = cc >> 4, oo = cc & 15;
                float s = b2[oo];
                for (int j = 0; j < HID; j++)
                    s += z2sm[ob * 129 + j] * W2[j * 16 + oo];
                if (m == 2) {
                    out[ob * 18 + 2 + oo] = s;
                } else if (oo == 15) {
                    out[ob * 18 + m] = s;
                    g_xpred[m][ob] = s;
                }
            }
            __threadfence();
            __syncthreads();
            if (m < 2 && tid == 0) atomicAdd(&g_xflag[m], 1);
        }
        return;
    }

    // ================= LSTM LAYER BLOCKS =================
    int layer, U, u0, NB;
    if (bid < NB0) { layer = 0; U = 8; NB = NB0; u0 = bid * 8; }
    else {
        layer = 1 + (bid - NB0) / NBL;
        int blk = (bid - NB0) % NBL;
        U = 4; NB = NBL; u0 = blk * 4;
    }
    const int NBbelow = (layer == 1) ? NB0 : NBL;

    // stage weights into SMEM (once)
    if (layer == 0) {
        for (int i = tid; i < 32 * 128; i += NTHR) {
            int r = i >> 7, k = i & 127;
            int R = (r >> 3) * HID + u0 + (r & 7);
            sW[r * 128 + k] = Whh[R * HID + k];
        }
        if (tid < 32) {
            int R = (tid >> 3) * HID + u0 + (tid & 7);
            sWx[tid] = Wih0[R];
            sB[tid]  = bih[R] + bhh[R];
        }
    } else {
        const float* wih = Wihr + (size_t)(layer - 1) * 512 * HID;
        const float* whh = Whh  + (size_t)layer * 512 * HID;
        for (int i = tid; i < 16 * 256; i += NTHR) {
            int r = i >> 8, k = i & 255;
            int R = (r >> 2) * HID + u0 + (r & 3);
            sW[r * 256 + k] = (k < 128) ? wih[R * HID + k] : whh[R * HID + (k - 128)];
        }
        if (tid < 16) {
            int R = (tid >> 2) * HID + u0 + (tid & 3);
            sB[tid] = bih[layer * 512 + R] + bhh[layer * 512 + R];
        }
    }
    __syncthreads();

    const int bp = tid & 15;            // batch pair index (batches 2bp, 2bp+1)
    int r0, r1 = -1;
    if (layer == 0) {                   // two combos per thread: gates g and g+2
        int g0 = tid >> 7;              // 0 or 1
        int uu = (tid >> 4) & 7;
        r0 = g0 * 8 + uu;
        r1 = (g0 + 2) * 8 + uu;
    } else {
        int g = tid >> 6;
        int uu = (tid >> 4) & 3;
        r0 = g * 4 + uu;
    }
    const bool isact = (layer == 0) ? (tid < 128) : (tid < 64);
    const int  au    = (layer == 0) ? ((tid >> 4) & 7) : ((tid >> 4) & 3);
    float2 cst = make_float2(0.0f, 0.0f);   // cell state for (au, bp)

    const float2* h2s = (const float2*)sH;

    for (int t = 0; t < TTOT; t++) {
        if (tid == 0) {
            if (layer > 0) waitflag(&g_hflag[layer - 1][t], NBbelow);
            else if (t >= TIN) waitflag(&g_xflag[t - TIN], 1);
            if (t > 0) waitflag(&g_hflag[layer][t - 1], NB);
        }
        __syncthreads();

        float2 a0 = make_float2(sB[r0], sB[r0]);
        float2 a1 = (layer == 0) ? make_float2(sB[r1], sB[r1]) : make_float2(0.f, 0.f);

        // ---- recurrent phase: W_hh . h(t-1) ----
        if (t > 0) {
            const float4* src = (const float4*)&g_h[layer][t - 1][0][0];
            float4* dst = (float4*)sH;
            for (int i = tid; i < 1024; i += NTHR) dst[i] = src[i];
            __syncthreads();
            if (layer == 0) {
                const float* w0 = sW + r0 * 128;
                const float* w1 = sW + r1 * 128;
                #pragma unroll 4
                for (int k = 0; k < 128; k++) {
                    float2 hv = h2s[k * 16 + bp];
                    a0 = ffma2(w0[k], hv, a0);
                    a1 = ffma2(w1[k], hv, a1);
                }
            } else {
                const float* w = sW + r0 * 256 + 128;
                #pragma unroll 8
                for (int k = 0; k < 128; k++)
                    a0 = ffma2(w[k], h2s[k * 16 + bp], a0);
            }
            __syncthreads();   // sH reuse barrier
        }

        // ---- input phase ----
        if (layer == 0) {
            float2 xv;
            if (t < TIN)
                xv = make_float2(x[(2 * bp) * TIN + t], x[(2 * bp + 1) * TIN + t]);
            else
                xv = make_float2(g_xpred[t - TIN][2 * bp], g_xpred[t - TIN][2 * bp + 1]);
            a0 = ffma2(sWx[r0], xv, a0);
            a1 = ffma2(sWx[r1], xv, a1);
        } else {
            const float4* src = (const float4*)&g_h[layer - 1][t][0][0];
            float4* dst = (float4*)sH;
            for (int i = tid; i < 1024; i += NTHR) dst[i] = src[i];
            __syncthreads();
            const float* w = sW + r0 * 256;
            #pragma unroll 8
            for (int k = 0; k < 128; k++)
                a0 = ffma2(w[k], h2s[k * 16 + bp], a0);
        }

        // ---- exchange gates, activate, publish h ----
        sG[r0 * 16 + bp] = a0;
        if (layer == 0) sG[r1 * 16 + bp] = a1;
        __syncthreads();

        if (isact) {
            float2 gi = sG[(0 * U + au) * 16 + bp];
            float2 gf = sG[(1 * U + au) * 16 + bp];
            float2 gg = sG[(2 * U + au) * 16 + bp];
            float2 go = sG[(3 * U + au) * 16 + bp];
            float2 hout;
            {
                float iv = sigm(gi.x), fv = sigm(gf.x);
                float gv = tanhf(gg.x), ov = sigm(go.x);
                cst.x = fv * cst.x + iv * gv;
                hout.x = ov * tanhf(cst.x);
            }
            {
                float iv = sigm(gi.y), fv = sigm(gf.y);
                float gv = tanhf(gg.y), ov = sigm(go.y);
                cst.y = fv * cst.y + iv * gv;
                hout.y = ov * tanhf(cst.y);
            }
            *(float2*)&g_h[layer][t][u0 + au][2 * bp] = hout;
        }
        __threadfence();
        __syncthreads();
        if (tid == 0) atomicAdd(&g_hflag[layer][t], 1);
    }
}

extern "C" void kernel_launch(void* const* d_in, const int* in_sizes, int n_in,
                              void* d_out, int out_size) {
    const float* x    = (const float*)d_in[0];
    // d_in[1] = future (int scalar) -- fixed at 18 by the problem; unused
    const float* Wih0 = (const float*)d_in[2];
    const float* Wihr = (const float*)d_in[3];
    const float* Whh  = (const float*)d_in[4];
    const float* bih  = (const float*)d_in[5];
    const float* bhh  = (const float*)d_in[6];
    const float* W1   = (const float*)d_in[7];
    const float* b1   = (const float*)d_in[8];
    const float* W2   = (const float*)d_in[9];
    const float* b2   = (const float*)d_in[10];
    float* out = (float*)d_out;

    zero_flags_kernel<<<11, 256>>>();
    lstm_main<<<GRID_N, NTHR>>>(x, Wih0, Wihr, Whh, bih, bhh, W1, b1, W2, b2, out);
}